// round 16
// baseline (speedup 1.0000x reference)
#include <cuda_runtime.h>
#include <cuda_bf16.h>
#include <mma.h>
#include <math_constants.h>

using namespace nvcuda;

// Problem dims
#define Bb   64
#define Ll   25
#define Ff   128
#define Pp   10000
#define Rr   (Bb*Ll)        // 1600 rows

// mega-kernel block ranges
#define NB_DM     1600
#define NB_DELTA  64
#define NB_TI     1
#define NB_QKV    (Bb*3)    // 192
#define NB_MEGA   (NB_DM + NB_DELTA + NB_TI + NB_QKV)

// ---------------- device scratch ----------------
// stats layout (int bits of nonnegative floats):
// 0 ds_max, 1 ds_min, 2 dt_max, 3 dt_min, 4 is_max, 5 is_min, 6 ti_max, 7 ti_min
__device__ int   g_stats[8];
__device__ float g_ti[Rr];
__device__ float g_q[Rr * Ff];
__device__ float g_k[Rr * Ff];
__device__ float g_v[Rr * Ff];
__device__ __nv_bfloat16 g_saoH[Rr * Ff];
__device__ __nv_bfloat16 g_saoR[Rr * Ff];
__device__ __nv_bfloat16 g_pwH[Pp * Ff];   // 2.56 MB
__device__ __nv_bfloat16 g_pwR[Pp * Ff];   // 2.56 MB

// ---------------- helpers ----------------
__device__ __forceinline__ float hav(float lat1, float lon1, float lat2, float lon2) {
    const float pc = 0.017453292519943295f;  // pi/180
    float a = 0.5f - cosf((lat2 - lat1) * pc) * 0.5f
            + cosf(lat1 * pc) * cosf(lat2 * pc) * (1.0f - cosf((lon2 - lon1) * pc)) * 0.5f;
    a = fminf(fmaxf(a, 0.0f), 1.0f);
    return 12742.0f * asinf(sqrtf(a));
}

__device__ __forceinline__ void blockMinMaxAtomic(float vmax, float vmin, int idxMax, int idxMin) {
    #pragma unroll
    for (int off = 16; off; off >>= 1) {
        vmax = fmaxf(vmax, __shfl_xor_sync(0xffffffffu, vmax, off));
        vmin = fminf(vmin, __shfl_xor_sync(0xffffffffu, vmin, off));
    }
    __shared__ float smax[8], smin[8];
    int warp = threadIdx.x >> 5, lane = threadIdx.x & 31;
    int nw = (blockDim.x + 31) >> 5;
    if (lane == 0) { smax[warp] = vmax; smin[warp] = vmin; }
    __syncthreads();
    if (warp == 0) {
        vmax = (lane < nw) ? smax[lane] : -CUDART_INF_F;
        vmin = (lane < nw) ? smin[lane] :  CUDART_INF_F;
        #pragma unroll
        for (int off = 4; off; off >>= 1) {
            vmax = fmaxf(vmax, __shfl_xor_sync(0xffffffffu, vmax, off));
            vmin = fminf(vmin, __shfl_xor_sync(0xffffffffu, vmin, off));
        }
        if (lane == 0) {
            atomicMax(&g_stats[idxMax], __float_as_int(vmax));
            atomicMin(&g_stats[idxMin], __float_as_int(vmin));
        }
    }
    __syncthreads();
}

// ---------------- launch 1: split pw into bf16 hi/res + init stats ----------------
__global__ void __launch_bounds__(256) k_prep(const float* __restrict__ pw) {
    if (blockIdx.x == 0 && threadIdx.x < 8)
        g_stats[threadIdx.x] = (threadIdx.x & 1) ? 0x7f800000 : 0;
    int i = blockIdx.x * 256 + threadIdx.x;           // one float4 per thread
    if (i < Pp * Ff / 4) {
        float4 v = ((const float4*)pw)[i];
        float xs[4] = {v.x, v.y, v.z, v.w};
        #pragma unroll
        for (int k = 0; k < 4; k++) {
            __nv_bfloat16 h = __float2bfloat16(xs[k]);
            g_pwH[i * 4 + k] = h;
            g_pwR[i * 4 + k] = __float2bfloat16(xs[k] - __bfloat162float(h));
        }
    }
}

// ---------------- launch 2: mega-kernel (dm stats | delta stats | ti | qkv) ----------------
__global__ void __launch_bounds__(256) k_mega(
    const int* __restrict__ poi, const float* __restrict__ dm,
    const float* __restrict__ lat, const float* __restrict__ lon, const float* __restrict__ ut,
    const int* __restrict__ user, const int* __restrict__ tod, const int* __restrict__ dow,
    const float* __restrict__ uw, const float* __restrict__ pw,
    const float* __restrict__ tw, const float* __restrict__ dww,
    const float* __restrict__ Wq, const float* __restrict__ bq,
    const float* __restrict__ Wk, const float* __restrict__ bk,
    const float* __restrict__ Wv, const float* __restrict__ bv) {
    int bid = blockIdx.x, tid = threadIdx.x;

    if (bid < NB_DM) {
        long row = poi[bid];
        const float4* r = (const float4*)(dm + row * (long)Pp);
        float vmax = -CUDART_INF_F, vmin = CUDART_INF_F;
        for (int c = tid; c < Pp / 4; c += 256) {
            float4 v = __ldg(&r[c]);
            vmax = fmaxf(vmax, fmaxf(fmaxf(v.x, v.y), fmaxf(v.z, v.w)));
            vmin = fminf(vmin, fminf(fminf(v.x, v.y), fminf(v.z, v.w)));
        }
        blockMinMaxAtomic(vmax, vmin, 4, 5);
        return;
    }
    if (bid < NB_DM + NB_DELTA) {
        int b = bid - NB_DM;
        const float* la = lat + b * Ll;
        const float* lo = lon + b * Ll;
        const float* u  = ut  + b * Ll;
        float dsmax = -CUDART_INF_F, dsmin = CUDART_INF_F;
        float dtmax = -CUDART_INF_F, dtmin = CUDART_INF_F;
        for (int idx = tid; idx < Ll * Ll; idx += 256) {
            int i = idx / Ll, j = idx % Ll;
            float ds = hav(la[i], lo[i], la[j], lo[j]);
            float dt = fabsf(u[i] - u[j]);
            dsmax = fmaxf(dsmax, ds); dsmin = fminf(dsmin, ds);
            dtmax = fmaxf(dtmax, dt); dtmin = fminf(dtmin, dt);
        }
        blockMinMaxAtomic(dsmax, dsmin, 0, 1);
        blockMinMaxAtomic(dtmax, dtmin, 2, 3);
        return;
    }
    if (bid < NB_DM + NB_DELTA + NB_TI) {
        float vmax = -CUDART_INF_F, vmin = CUDART_INF_F;
        for (int i = tid; i < Rr; i += 256) {
            int l = i % Ll;
            float t = (l == 0) ? 0.0f : fabsf(ut[i] - ut[i - 1]);
            g_ti[i] = t;
            vmax = fmaxf(vmax, t); vmin = fminf(vmin, t);
        }
        blockMinMaxAtomic(vmax, vmin, 6, 7);
        return;
    }

    // -------- qkv: block = (b, z), halves of L via tid>>7; 13 accs/thread --------
    {
        int qi = bid - (NB_DM + NB_DELTA + NB_TI);
        int b = qi / 3, z = qi % 3;
        int half = tid >> 7, f = tid & 127;
        int l0 = half * 13;
        int nl = half ? 12 : 13;
        __shared__ float inp_s[2][13][Ff];

        for (int i = f; i < 13 * Ff; i += 128) {
            int l = i >> 7, ff = i & 127;
            float v = 0.0f;
            if (l < nl) {
                int base = b * Ll + l0 + l;
                v = uw[user[base] * Ff + ff] + pw[poi[base] * Ff + ff]
                  + tw[tod[base] * Ff + ff]  + dww[dow[base] * Ff + ff];
            }
            inp_s[half][l][ff] = v;
        }
        __syncthreads();

        const float* W    = (z == 0) ? Wq : (z == 1) ? Wk : Wv;
        const float* bias = (z == 0) ? bq : (z == 1) ? bk : bv;
        float*       dst  = (z == 0) ? g_q : (z == 1) ? g_k : g_v;

        float a[13];
        #pragma unroll
        for (int l = 0; l < 13; l++) a[l] = 0.f;
        #pragma unroll 4
        for (int g = 0; g < Ff; g++) {
            float w = W[g * Ff + f];
            #pragma unroll
            for (int l = 0; l < 13; l++) a[l] = fmaf(inp_s[half][l][g], w, a[l]);
        }
        float bf = bias[f];
        #pragma unroll
        for (int l = 0; l < 13; l++)
            if (l < nl) dst[(b * Ll + l0 + l) * Ff + f] = a[l] + bf;
    }
}

// ---------------- launch 3: scores + delta + softmax + attn@v ----------------
__global__ void __launch_bounds__(128) k_attn2(
    const float* __restrict__ lat, const float* __restrict__ lon, const float* __restrict__ ut) {
    __shared__ float q_s[Ll][132];
    __shared__ float k_s[Ll][132];
    __shared__ float sc[Ll][26];
    int b = blockIdx.x, tid = threadIdx.x;

    for (int i = tid; i < Ll * Ff; i += 128) {
        int l = i >> 7, f = i & 127;
        q_s[l][f] = g_q[(b * Ll + l) * Ff + f];
        k_s[l][f] = g_k[(b * Ll + l) * Ff + f];
    }
    int f = tid;
    float av[Ll];
    #pragma unroll
    for (int l = 0; l < Ll; l++) av[l] = g_v[(b * Ll + l) * Ff + f];
    __syncthreads();

    float invDs = 1.0f / (__int_as_float(g_stats[0]) - __int_as_float(g_stats[1]));
    float invDt = 1.0f / (__int_as_float(g_stats[2]) - __int_as_float(g_stats[3]));
    for (int idx = tid; idx < Ll * Ll; idx += 128) {
        int i = idx / Ll, j = idx % Ll;
        float s0 = 0.f, s1 = 0.f, s2 = 0.f, s3 = 0.f;
        #pragma unroll 8
        for (int f2 = 0; f2 < Ff; f2 += 4) {
            s0 = fmaf(q_s[i][f2 + 0], k_s[j][f2 + 0], s0);
            s1 = fmaf(q_s[i][f2 + 1], k_s[j][f2 + 1], s1);
            s2 = fmaf(q_s[i][f2 + 2], k_s[j][f2 + 2], s2);
            s3 = fmaf(q_s[i][f2 + 3], k_s[j][f2 + 3], s3);
        }
        float s = (s0 + s1) + (s2 + s3);
        int bi = b * Ll + i, bj = b * Ll + j;
        float ds = hav(lat[bi], lon[bi], lat[bj], lon[bj]);
        float dt = fabsf(ut[bi] - ut[bj]);
        sc[i][j] = s + 0.5f * (__expf(-ds * invDs) + __expf(-dt * invDt));
    }
    __syncthreads();

    if (tid < Ll) {
        float m = -CUDART_INF_F;
        for (int j = 0; j < Ll; j++) m = fmaxf(m, sc[tid][j]);
        float sum = 0.f;
        for (int j = 0; j < Ll; j++) sum += __expf(sc[tid][j] - m);
        float inv = 1.0f / sum;
        for (int j = 0; j < Ll; j++) sc[tid][j] = __expf(sc[tid][j] - m) * inv;
    }
    __syncthreads();

    for (int i = 0; i < Ll; i++) {
        float acc = 0.f;
        #pragma unroll
        for (int j = 0; j < Ll; j++) acc = fmaf(sc[i][j], av[j], acc);
        int idx = (b * Ll + i) * Ff + f;
        __nv_bfloat16 h = __float2bfloat16(acc);
        g_saoH[idx] = h;
        g_saoR[idx] = __float2bfloat16(acc - __bfloat162float(h));
    }
}

// ---------------- launch 4: fused GEMM (split-bf16, fully restaged) + epilogue ----------------
// S(64x128) = sao(2 batches, padded 25->32 rows) @ pw^T tile.
// ONE A buffer (64x136) + ONE B buffer (128x136) = 52224 B smem; three passes
// restage between them: [A=aH,B=bH]:aH*bH -> [A=aR]:aR*bH -> [A=aH,B=bR]:aH*bR.
// Accumulators persist in registers across passes. Restage reads are L2-hot
// (g_sao* 800KB, g_pw* 2.5MB). __launch_bounds__(256,3) -> 3 blocks/SM = 24 warps
// (vs 16 at R11's 69.6KB), attacking the measured L1/latency bound (occ 34.5%).
#define SMEM_FUSED 52224

__global__ void __launch_bounds__(256, 3) k_fused(
    const int* __restrict__ poi,
    const float* __restrict__ dm, const float* __restrict__ wval,
    const float* __restrict__ bval, float* __restrict__ out, int dup) {
    extern __shared__ char smraw[];
    __nv_bfloat16* As = (__nv_bfloat16*)smraw;          // 64*136*2  = 17408 B
    __nv_bfloat16* Bs = (__nv_bfloat16*)(smraw + 17408);// 128*136*2 = 34816 B
    float* S = (float*)smraw;                           // 64*128*4 = 32768 B, overlays after MMA
    __shared__ int   prow[2][Ll];
    __shared__ float cw[Ll], e2[2][Ll];

    int tid = threadIdx.x;
    int colTile = blockIdx.x * 128;
    int b0 = blockIdx.y * 2;

    if (tid < 2 * Ll) {
        int bt = tid / Ll, l = tid % Ll;
        int b = b0 + bt;
        prow[bt][l] = poi[b * Ll + l];
        float T1 = __int_as_float(g_stats[6]) - __int_as_float(g_stats[7]);
        e2[bt][l] = __expf(-g_ti[b * Ll + l] / T1);
        if (bt == 0) cw[l] = 0.5f * wval[l];
    }

    // ---- stage A = saoH, B = pwH ----
    for (int i = tid; i < 64 * 16; i += 256) {
        int r = i >> 4, c8 = (i & 15) << 3;
        int bt = r >> 5, l = r & 31;
        uint4 v = make_uint4(0, 0, 0, 0);
        if (l < Ll) v = *(const uint4*)(g_saoH + ((long)(b0 + bt) * Ll + l) * Ff + c8);
        *(uint4*)(As + r * 136 + c8) = v;
    }
    for (int i = tid; i < 128 * 16; i += 256) {
        int r = i >> 4, c8 = (i & 15) << 3;
        int p = colTile + r;
        uint4 v = make_uint4(0, 0, 0, 0);
        if (p < Pp) v = *(const uint4*)(g_pwH + (long)p * Ff + c8);
        *(uint4*)(Bs + r * 136 + c8) = v;
    }
    __syncthreads();

    int w = tid >> 5, wm = w >> 2, wn = w & 3;   // 2x4 warps: each 32 rows x 32 cols
    wmma::fragment<wmma::accumulator, 16, 16, 16, float> acc[2][2];
    #pragma unroll
    for (int i = 0; i < 2; i++)
        #pragma unroll
        for (int j = 0; j < 2; j++) wmma::fill_fragment(acc[i][j], 0.0f);

    // ---- pass 1: aH * bH ----
    #pragma unroll
    for (int kk = 0; kk < Ff; kk += 16) {
        wmma::fragment<wmma::matrix_a, 16, 16, 16, __nv_bfloat16, wmma::row_major> af[2];
        wmma::fragment<wmma::matrix_b, 16, 16, 16, __nv_bfloat16, wmma::col_major> bf[2];
        #pragma unroll
        for (int i = 0; i < 2; i++)
            wmma::load_matrix_sync(af[i], As + (wm * 32 + i * 16) * 136 + kk, 136);
        #pragma unroll
        for (int j = 0; j < 2; j++)
            wmma::load_matrix_sync(bf[j], Bs + (wn * 32 + j * 16) * 136 + kk, 136);
        #pragma unroll
        for (int i = 0; i < 2; i++)
            #pragma unroll
            for (int j = 0; j < 2; j++)
                wmma::mma_sync(acc[i][j], af[i], bf[j], acc[i][j]);
    }
    __syncthreads();

    // ---- restage A = saoR ----
    for (int i = tid; i < 64 * 16; i += 256) {
        int r = i >> 4, c8 = (i & 15) << 3;
        int bt = r >> 5, l = r & 31;
        uint4 v = make_uint4(0, 0, 0, 0);
        if (l < Ll) v = *(const uint4*)(g_saoR + ((long)(b0 + bt) * Ll + l) * Ff + c8);
        *(uint4*)(As + r * 136 + c8) = v;
    }
    __syncthreads();

    // ---- pass 2: aR * bH ----
    #pragma unroll
    for (int kk = 0; kk < Ff; kk += 16) {
        wmma::fragment<wmma::matrix_a, 16, 16, 16, __nv_bfloat16, wmma::row_major> af[2];
        wmma::fragment<wmma::matrix_b, 16, 16, 16, __nv_bfloat16, wmma::col_major> bf[2];
        #pragma unroll
        for (int i = 0; i < 2; i++)
            wmma::load_matrix_sync(af[i], As + (wm * 32 + i * 16) * 136 + kk, 136);
        #pragma unroll
        for (int j = 0; j < 2; j++)
            wmma::load_matrix_sync(bf[j], Bs + (wn * 32 + j * 16) * 136 + kk, 136);
        #pragma unroll
        for (int i = 0; i < 2; i++)
            #pragma unroll
            for (int j = 0; j < 2; j++)
                wmma::mma_sync(acc[i][j], af[i], bf[j], acc[i][j]);
    }
    __syncthreads();

    // ---- restage A = saoH, B = pwR ----
    for (int i = tid; i < 64 * 16; i += 256) {
        int r = i >> 4, c8 = (i & 15) << 3;
        int bt = r >> 5, l = r & 31;
        uint4 v = make_uint4(0, 0, 0, 0);
        if (l < Ll) v = *(const uint4*)(g_saoH + ((long)(b0 + bt) * Ll + l) * Ff + c8);
        *(uint4*)(As + r * 136 + c8) = v;
    }
    for (int i = tid; i < 128 * 16; i += 256) {
        int r = i >> 4, c8 = (i & 15) << 3;
        int p = colTile + r;
        uint4 v = make_uint4(0, 0, 0, 0);
        if (p < Pp) v = *(const uint4*)(g_pwR + (long)p * Ff + c8);
        *(uint4*)(Bs + r * 136 + c8) = v;
    }
    __syncthreads();

    // ---- pass 3: aH * bR ----
    #pragma unroll
    for (int kk = 0; kk < Ff; kk += 16) {
        wmma::fragment<wmma::matrix_a, 16, 16, 16, __nv_bfloat16, wmma::row_major> af[2];
        wmma::fragment<wmma::matrix_b, 16, 16, 16, __nv_bfloat16, wmma::col_major> bf[2];
        #pragma unroll
        for (int i = 0; i < 2; i++)
            wmma::load_matrix_sync(af[i], As + (wm * 32 + i * 16) * 136 + kk, 136);
        #pragma unroll
        for (int j = 0; j < 2; j++)
            wmma::load_matrix_sync(bf[j], Bs + (wn * 32 + j * 16) * 136 + kk, 136);
        #pragma unroll
        for (int i = 0; i < 2; i++)
            #pragma unroll
            for (int j = 0; j < 2; j++)
                wmma::mma_sync(acc[i][j], af[i], bf[j], acc[i][j]);
    }
    __syncthreads();   // all frag reads done before S overlays the operand buffers

    #pragma unroll
    for (int i = 0; i < 2; i++)
        #pragma unroll
        for (int j = 0; j < 2; j++)
            wmma::store_matrix_sync(S + (wm * 32 + i * 16) * 128 + wn * 32 + j * 16,
                                    acc[i][j], 128, wmma::mem_row_major);
    __syncthreads();

    // epilogue: 256 threads -> thread = (p column, batch); 25 independent dm loads each
    int col = tid & 127, bt = tid >> 7;
    int p = colTile + col;
    if (p < Pp) {
        float invS1 = 1.0f / (__int_as_float(g_stats[4]) - __int_as_float(g_stats[5]));
        float a2 = bval[0];
        #pragma unroll
        for (int l = 0; l < Ll; l++) {
            float m = S[(bt * 32 + l) * 128 + col];
            float d = dm[(long)prow[bt][l] * Pp + p];
            a2 = fmaf(cw[l] * m, __expf(-d * invS1) + e2[bt][l], a2);
        }
        int b = b0 + bt;
        out[b * Pp + p] = a2;
        if (dup) out[Bb * Pp + b * Pp + p] = a2;
    }
}

// ---------------- launch ----------------
extern "C" void kernel_launch(void* const* d_in, const int* in_sizes, int n_in,
                              void* d_out, int out_size) {
    const int*   user = (const int*)  d_in[0];
    const int*   poi  = (const int*)  d_in[1];
    // d_in[2] = cat (unused by reference)
    const float* lat  = (const float*)d_in[3];
    const float* lon  = (const float*)d_in[4];
    const int*   tod  = (const int*)  d_in[5];
    const int*   dow  = (const int*)  d_in[6];
    const float* ut   = (const float*)d_in[7];
    const float* uw   = (const float*)d_in[8];
    const float* pw   = (const float*)d_in[9];
    const float* tw   = (const float*)d_in[10];
    const float* dww  = (const float*)d_in[11];
    const float* Wq   = (const float*)d_in[12];
    const float* bq   = (const float*)d_in[13];
    const float* Wk   = (const float*)d_in[14];
    const float* bk   = (const float*)d_in[15];
    const float* Wv   = (const float*)d_in[16];
    const float* bv   = (const float*)d_in[17];
    const float* wval = (const float*)d_in[18];
    const float* bval = (const float*)d_in[19];
    const float* dm   = (const float*)d_in[20];
    float* out = (float*)d_out;
    int dup = (out_size >= 2 * Bb * Pp) ? 1 : 0;

    cudaFuncSetAttribute(k_fused, cudaFuncAttributeMaxDynamicSharedMemorySize, SMEM_FUSED);

    k_prep<<<(Pp * Ff / 4 + 255) / 256, 256>>>(pw);                       // launch 1
    k_mega<<<NB_MEGA, 256>>>(poi, dm, lat, lon, ut, user, tod, dow,       // launch 2
                             uw, pw, tw, dww, Wq, bq, Wk, bk, Wv, bv);
    k_attn2<<<Bb, 128>>>(lat, lon, ut);                                   // launch 3
    k_fused<<<dim3(79, Bb / 2), 256, SMEM_FUSED>>>(poi, dm, wval, bval,   // launch 4
                                                   out, dup);
}